// round 3
// baseline (speedup 1.0000x reference)
#include <cuda_runtime.h>

#define H 128
#define NNODE 100000

// ---- scratch (device globals: no allocation allowed) ----
__device__ float g_agg[NNODE * H];
__device__ float g_xi1[NNODE * H];
__device__ float g_xu1[NNODE * H];
__device__ float g_xi2[NNODE * H];
__device__ float g_xu2[NNODE * H];
__device__ float g_inv_i[NNODE];
__device__ float g_inv_u[NNODE];

// ---------------------------------------------------------------------------
__global__ void zero4_kernel(float4* p, int n4) {
    int i = blockIdx.x * blockDim.x + threadIdx.x;
    if (i < n4) p[i] = make_float4(0.f, 0.f, 0.f, 0.f);
}

__global__ void count_kernel(const int* __restrict__ dst, float* cnt, int E) {
    int i = blockIdx.x * blockDim.x + threadIdx.x;
    if (i < E) atomicAdd(&cnt[dst[i]], 1.0f);
}

__global__ void inv_kernel(float* p, int n) {
    int i = blockIdx.x * blockDim.x + threadIdx.x;
    if (i < n) p[i] = 1.0f / fmaxf(p[i], 1.0f);
}

__device__ __forceinline__ void red_add_v4(float* addr, float4 v) {
    asm volatile("red.global.add.v4.f32 [%0], {%1, %2, %3, %4};"
                 :: "l"(addr), "f"(v.x), "f"(v.y), "f"(v.z), "f"(v.w)
                 : "memory");
}

// one warp per edge: gather 512B row, vector-RED into agg[dst]
__global__ void scatter_kernel(const float* __restrict__ xsrc,
                               const int* __restrict__ src,
                               const int* __restrict__ dst,
                               float* __restrict__ agg, int E) {
    int gt = blockIdx.x * blockDim.x + threadIdx.x;
    int e = gt >> 5;
    if (e >= E) return;
    int lane = gt & 31;
    int s = __ldg(&src[e]);
    int d = __ldg(&dst[e]);
    float4 v = __ldg(((const float4*)(xsrc + (long)s * H)) + lane);
    red_add_v4(agg + (long)d * H + lane * 4, v);
}

// ---------------------------------------------------------------------------
// Fused SAGEConv GEMM: out[m, :] = mean[m,:] @ Wl + bias + xdst[m,:] @ Wr
// As single GEMM: A = [mean || xdst]  (M x 256),  B = [Wl ; Wr]  (256 x 128)
// Tile: 128 rows x 128 cols per block, 256 threads, 8x8 per thread, K-chunk 32.
__global__ void __launch_bounds__(256, 2)
conv_gemm_kernel(const float* __restrict__ agg, const float* __restrict__ inv,
                 const float* __restrict__ xdst,
                 const float* __restrict__ wl, const float* __restrict__ wr,
                 const float* __restrict__ bias,
                 float* __restrict__ out, int M) {
    __shared__ float As[32][128];   // [k][m] transposed
    __shared__ float Bs[32][128];   // [k][j]

    int t = threadIdx.x;
    int tcol = t & 15;   // 16 col-groups * 8 cols = 128
    int trow = t >> 4;   // 16 row-groups * 8 rows = 128
    int m0 = blockIdx.x * 128;

    float acc[8][8];
#pragma unroll
    for (int r = 0; r < 8; ++r)
#pragma unroll
        for (int c = 0; c < 8; ++c) acc[r][c] = 0.f;

    for (int kc = 0; kc < 8; ++kc) {
        const bool mean_part = (kc < 4);
        const int kbase = (kc & 3) * 32;
        const float* asrc = mean_part ? agg : xdst;
        const float* bsrc = mean_part ? wl : wr;

        // load A chunk: 128 rows x 32 k = 1024 float4, 4 per thread
#pragma unroll
        for (int i = 0; i < 4; ++i) {
            int idx = t * 4 + i;
            int row = idx >> 3;   // 8 float4 per row
            int k4  = idx & 7;
            int m = m0 + row;
            float4 v = make_float4(0.f, 0.f, 0.f, 0.f);
            if (m < M) {
                v = *(const float4*)(asrc + (long)m * H + kbase + k4 * 4);
                if (mean_part) {
                    float s = inv[m];
                    v.x *= s; v.y *= s; v.z *= s; v.w *= s;
                }
            }
            int k = k4 * 4;
            As[k + 0][row] = v.x;
            As[k + 1][row] = v.y;
            As[k + 2][row] = v.z;
            As[k + 3][row] = v.w;
        }
        // load B chunk: 32 k-rows x 32 float4, 4 per thread
#pragma unroll
        for (int i = 0; i < 4; ++i) {
            int idx = t * 4 + i;
            int row = idx >> 5;   // 32 float4 per row
            int c4  = idx & 31;
            float4 v = *(const float4*)(bsrc + (long)(kbase + row) * H + c4 * 4);
            *(float4*)&Bs[row][c4 * 4] = v;
        }
        __syncthreads();

#pragma unroll 8
        for (int k = 0; k < 32; ++k) {
            float4 a0 = *(const float4*)&As[k][trow * 8];
            float4 a1 = *(const float4*)&As[k][trow * 8 + 4];
            float4 b0 = *(const float4*)&Bs[k][tcol * 8];
            float4 b1 = *(const float4*)&Bs[k][tcol * 8 + 4];
            float a[8] = {a0.x, a0.y, a0.z, a0.w, a1.x, a1.y, a1.z, a1.w};
            float b[8] = {b0.x, b0.y, b0.z, b0.w, b1.x, b1.y, b1.z, b1.w};
#pragma unroll
            for (int r = 0; r < 8; ++r)
#pragma unroll
                for (int c = 0; c < 8; ++c)
                    acc[r][c] = fmaf(a[r], b[c], acc[r][c]);
        }
        __syncthreads();
    }

    // epilogue: + bias, store raw (normalize+relu is a separate pass)
#pragma unroll
    for (int r = 0; r < 8; ++r) {
        int m = m0 + trow * 8 + r;
        if (m >= M) continue;
#pragma unroll
        for (int c = 0; c < 8; c += 4) {
            int j = tcol * 8 + c;
            float4 o;
            o.x = acc[r][c + 0] + bias[j + 0];
            o.y = acc[r][c + 1] + bias[j + 1];
            o.z = acc[r][c + 2] + bias[j + 2];
            o.w = acc[r][c + 3] + bias[j + 3];
            *(float4*)(out + (long)m * H + j) = o;
        }
    }
}

// ---------------------------------------------------------------------------
// L2-normalize each row (eps=1e-12) then relu, in place. One warp per row.
__global__ void norm_relu_kernel(float* __restrict__ x, int M) {
    int row = blockIdx.x * 8 + (threadIdx.x >> 5);
    if (row >= M) return;
    int lane = threadIdx.x & 31;
    float4* p = ((float4*)(x + (long)row * H)) + lane;
    float4 v = *p;
    float s = v.x * v.x + v.y * v.y + v.z * v.z + v.w * v.w;
#pragma unroll
    for (int o = 16; o; o >>= 1) s += __shfl_xor_sync(0xffffffffu, s, o);
    float scale = 1.0f / fmaxf(sqrtf(s), 1e-12f);
    v.x = fmaxf(v.x * scale, 0.f);
    v.y = fmaxf(v.y * scale, 0.f);
    v.z = fmaxf(v.z * scale, 0.f);
    v.w = fmaxf(v.w * scale, 0.f);
    *p = v;
}

// one warp per labeled edge: dot(xu2[src], xi2[dst])
__global__ void classifier_kernel(const float* __restrict__ xu,
                                  const float* __restrict__ xi,
                                  const int* __restrict__ lsrc,
                                  const int* __restrict__ ldst,
                                  float* __restrict__ out, int L) {
    int e = blockIdx.x * 8 + (threadIdx.x >> 5);
    if (e >= L) return;
    int lane = threadIdx.x & 31;
    int s = __ldg(&lsrc[e]);
    int d = __ldg(&ldst[e]);
    float4 a = __ldg(((const float4*)(xu + (long)s * H)) + lane);
    float4 b = __ldg(((const float4*)(xi + (long)d * H)) + lane);
    float v = a.x * b.x + a.y * b.y + a.z * b.z + a.w * b.w;
#pragma unroll
    for (int o = 16; o; o >>= 1) v += __shfl_xor_sync(0xffffffffu, v, o);
    if (lane == 0) out[e] = v;
}

// ---------------------------------------------------------------------------
extern "C" void kernel_launch(void* const* d_in, const int* in_sizes, int n_in,
                              void* d_out, int out_size) {
    const float* emb_u = (const float*)d_in[0];
    const float* emb_i = (const float*)d_in[1];
    const int* er  = (const int*)d_in[2];   // edge_rates [2, E]
    const int* erv = (const int*)d_in[3];   // edge_rev   [2, E]
    const int* lbl = (const int*)d_in[4];   // edge_label_index [2, L]
    const float* w1l_rates = (const float*)d_in[5];
    const float* w1r_rates = (const float*)d_in[6];
    const float* w1l_rev   = (const float*)d_in[7];
    const float* w1r_rev   = (const float*)d_in[8];
    const float* w2l_rates = (const float*)d_in[9];
    const float* w2r_rates = (const float*)d_in[10];
    const float* w2l_rev   = (const float*)d_in[11];
    const float* w2r_rev   = (const float*)d_in[12];
    const float* b1_rates  = (const float*)d_in[13];
    const float* b1_rev    = (const float*)d_in[14];
    const float* b2_rates  = (const float*)d_in[15];
    const float* b2_rev    = (const float*)d_in[16];
    float* out = (float*)d_out;

    const int E = in_sizes[2] / 2;
    const int L = in_sizes[4] / 2;

    float *agg, *xi1, *xu1, *xi2, *xu2, *inv_i, *inv_u;
    cudaGetSymbolAddress((void**)&agg,   g_agg);
    cudaGetSymbolAddress((void**)&xi1,   g_xi1);
    cudaGetSymbolAddress((void**)&xu1,   g_xu1);
    cudaGetSymbolAddress((void**)&xi2,   g_xi2);
    cudaGetSymbolAddress((void**)&xu2,   g_xu2);
    cudaGetSymbolAddress((void**)&inv_i, g_inv_i);
    cudaGetSymbolAddress((void**)&inv_u, g_inv_u);

    const int NB_FEAT4 = (NNODE * H / 4 + 255) / 256;   // zero agg (float4)
    const int NB_CNT4  = (NNODE / 4 + 255) / 256;
    const int NB_E     = (E + 255) / 256;
    const int NB_SCAT  = ((E * 32) + 255) / 256;
    const int NB_GEMM  = (NNODE + 127) / 128;
    const int NB_ROWS  = (NNODE + 7) / 8;
    const int NB_L     = (L + 7) / 8;

    // degree counts -> inverse (shared by both layers)
    zero4_kernel<<<NB_CNT4, 256>>>((float4*)inv_i, NNODE / 4);
    zero4_kernel<<<NB_CNT4, 256>>>((float4*)inv_u, NNODE / 4);
    count_kernel<<<NB_E, 256>>>(er + E,  inv_i, E);
    count_kernel<<<NB_E, 256>>>(erv + E, inv_u, E);
    inv_kernel<<<(NNODE + 255) / 256, 256>>>(inv_i, NNODE);
    inv_kernel<<<(NNODE + 255) / 256, 256>>>(inv_u, NNODE);

    // ---- layer 1: items <- users over edge_rates ----
    zero4_kernel<<<NB_FEAT4, 256>>>((float4*)agg, NNODE * H / 4);
    scatter_kernel<<<NB_SCAT, 256>>>(emb_u, er, er + E, agg, E);
    conv_gemm_kernel<<<NB_GEMM, 256>>>(agg, inv_i, emb_i, w1l_rates, w1r_rates,
                                       b1_rates, xi1, NNODE);
    norm_relu_kernel<<<NB_ROWS, 256>>>(xi1, NNODE);

    // ---- layer 1: users <- items over edge_rev ----
    zero4_kernel<<<NB_FEAT4, 256>>>((float4*)agg, NNODE * H / 4);
    scatter_kernel<<<NB_SCAT, 256>>>(emb_i, erv, erv + E, agg, E);
    conv_gemm_kernel<<<NB_GEMM, 256>>>(agg, inv_u, emb_u, w1l_rev, w1r_rev,
                                       b1_rev, xu1, NNODE);
    norm_relu_kernel<<<NB_ROWS, 256>>>(xu1, NNODE);

    // ---- layer 2: items <- users ----
    zero4_kernel<<<NB_FEAT4, 256>>>((float4*)agg, NNODE * H / 4);
    scatter_kernel<<<NB_SCAT, 256>>>(xu1, er, er + E, agg, E);
    conv_gemm_kernel<<<NB_GEMM, 256>>>(agg, inv_i, xi1, w2l_rates, w2r_rates,
                                       b2_rates, xi2, NNODE);
    norm_relu_kernel<<<NB_ROWS, 256>>>(xi2, NNODE);

    // ---- layer 2: users <- items ----
    zero4_kernel<<<NB_FEAT4, 256>>>((float4*)agg, NNODE * H / 4);
    scatter_kernel<<<NB_SCAT, 256>>>(xi1, erv, erv + E, agg, E);
    conv_gemm_kernel<<<NB_GEMM, 256>>>(agg, inv_u, xu1, w2l_rev, w2r_rev,
                                       b2_rev, xu2, NNODE);
    norm_relu_kernel<<<NB_ROWS, 256>>>(xu2, NNODE);

    // ---- classifier ----
    classifier_kernel<<<NB_L, 256>>>(xu2, xi2, lbl, lbl + L, out, L);
}

// round 5
// speedup vs baseline: 1.4066x; 1.4066x over previous
#include <cuda_runtime.h>

#define H 128
#define NNODE 100000
#define EMAX 1600000
#define SCAN_BS 1024
#define SCAN_NB ((NNODE + SCAN_BS - 1) / SCAN_BS)   // 98

typedef unsigned long long ull;

// ---- scratch (device globals: no allocation allowed) ----
__device__ float g_mean[NNODE * H];
__device__ float g_xi1[NNODE * H];
__device__ float g_xu1[NNODE * H];
__device__ float g_xi2[NNODE * H];
__device__ float g_xu2[NNODE * H];
__device__ int g_cnt[2][NNODE];
__device__ int g_off[2][NNODE + 1];
__device__ int g_cur[2][NNODE];
__device__ int g_csr[2][EMAX];
__device__ int g_bsum[2][SCAN_NB];

// ---------------------------------------------------------------------------
__global__ void zero_int4_kernel(int4* p, int n4) {
    int i = blockIdx.x * blockDim.x + threadIdx.x;
    if (i < n4) p[i] = make_int4(0, 0, 0, 0);
}

__global__ void count_kernel(const int* __restrict__ dst, int* cnt, int E) {
    int i = blockIdx.x * blockDim.x + threadIdx.x;
    if (i < E) atomicAdd(&cnt[dst[i]], 1);
}

// phase 1: per-block exclusive scan, emit block sums
__global__ void scan_block_kernel(const int* __restrict__ cnt, int* off,
                                  int* bsum, int n) {
    __shared__ int sh[SCAN_BS];
    int tid = threadIdx.x;
    int gid = blockIdx.x * SCAN_BS + tid;
    int v = (gid < n) ? cnt[gid] : 0;
    sh[tid] = v;
    __syncthreads();
#pragma unroll
    for (int o = 1; o < SCAN_BS; o <<= 1) {
        int t = (tid >= o) ? sh[tid - o] : 0;
        __syncthreads();
        sh[tid] += t;
        __syncthreads();
    }
    if (gid < n) off[gid] = sh[tid] - v;   // exclusive
    if (tid == SCAN_BS - 1) bsum[blockIdx.x] = sh[tid];
}

// phase 2: single-block exclusive scan of block sums (nb <= 128)
__global__ void scan_sums_kernel(int* bsum, int nb) {
    __shared__ int sh[128];
    int tid = threadIdx.x;
    int v = (tid < nb) ? bsum[tid] : 0;
    sh[tid] = v;
    __syncthreads();
#pragma unroll
    for (int o = 1; o < 128; o <<= 1) {
        int t = (tid >= o) ? sh[tid - o] : 0;
        __syncthreads();
        sh[tid] += t;
        __syncthreads();
    }
    if (tid < nb) bsum[tid] = sh[tid] - v;
}

// phase 3: add block offsets; also init cursor and off[n]=E
__global__ void finalize_off_kernel(int* off, int* cur,
                                    const int* __restrict__ bsum, int n, int E) {
    int gid = blockIdx.x * blockDim.x + threadIdx.x;
    if (gid < n) {
        int o = off[gid] + bsum[gid >> 10];
        off[gid] = o;
        cur[gid] = o;
    }
    if (gid == 0) off[n] = E;
}

__global__ void fill_csr_kernel(const int* __restrict__ src,
                                const int* __restrict__ dst,
                                int* cur, int* __restrict__ csr, int E) {
    int e = blockIdx.x * blockDim.x + threadIdx.x;
    if (e >= E) return;
    int d = __ldg(&dst[e]);
    int pos = atomicAdd(&cur[d], 1);
    csr[pos] = __ldg(&src[e]);
}

// ---------------------------------------------------------------------------
// One warp per dst row: gather neighbor rows, accumulate in regs, write mean.
__global__ void gather_mean_kernel(const float* __restrict__ xsrc,
                                   const int* __restrict__ off,
                                   const int* __restrict__ csr,
                                   float* __restrict__ mean, int M) {
    int row = blockIdx.x * 8 + (threadIdx.x >> 5);
    if (row >= M) return;
    int lane = threadIdx.x & 31;
    int beg = __ldg(&off[row]);
    int end = __ldg(&off[row + 1]);
    float4 a0 = make_float4(0.f, 0.f, 0.f, 0.f);
    float4 a1 = make_float4(0.f, 0.f, 0.f, 0.f);
    int j = beg;
    for (; j + 1 < end; j += 2) {
        int s0 = __ldg(&csr[j]);
        int s1 = __ldg(&csr[j + 1]);
        float4 v0 = __ldg(((const float4*)(xsrc + (long)s0 * H)) + lane);
        float4 v1 = __ldg(((const float4*)(xsrc + (long)s1 * H)) + lane);
        a0.x += v0.x; a0.y += v0.y; a0.z += v0.z; a0.w += v0.w;
        a1.x += v1.x; a1.y += v1.y; a1.z += v1.z; a1.w += v1.w;
    }
    if (j < end) {
        int s0 = __ldg(&csr[j]);
        float4 v0 = __ldg(((const float4*)(xsrc + (long)s0 * H)) + lane);
        a0.x += v0.x; a0.y += v0.y; a0.z += v0.z; a0.w += v0.w;
    }
    float inv = 1.0f / fmaxf((float)(end - beg), 1.0f);
    float4 o;
    o.x = (a0.x + a1.x) * inv;
    o.y = (a0.y + a1.y) * inv;
    o.z = (a0.z + a1.z) * inv;
    o.w = (a0.w + a1.w) * inv;
    *(((float4*)(mean + (long)row * H)) + lane) = o;
}

// ---------------------------------------------------------------------------
__device__ __forceinline__ ull ffma2(ull a, ull b, ull c) {
    ull d;
    asm("fma.rn.f32x2 %0, %1, %2, %3;" : "=l"(d) : "l"(a), "l"(b), "l"(c));
    return d;
}

// Fused SAGEConv GEMM with packed f32x2 FMA:
// out[m,:] = mean[m,:] @ Wl + bias + xdst[m,:] @ Wr
// A = [mean || xdst] (M x 256), B = [Wl ; Wr] (256 x 128)
// Tile 128x128, 256 threads, 8x8 per thread (4 packed col-pairs), K-chunk 16.
// A tile stored DUPLICATED in smem so {a,a} broadcast pairs come from LDS.
__global__ void __launch_bounds__(256, 2)
conv_gemm_kernel(const float* __restrict__ meanA,
                 const float* __restrict__ xdst,
                 const float* __restrict__ wl, const float* __restrict__ wr,
                 const float* __restrict__ bias,
                 float* __restrict__ out, int M) {
    __shared__ float As2[16][256];   // [k][2*m] duplicated pairs (16 KB)
    __shared__ float Bs[16][128];    // [k][j]                    (8 KB)

    int t = threadIdx.x;
    int tcol = t & 15;   // 16 col-groups * 8 cols
    int trow = t >> 4;   // 16 row-groups * 8 rows
    int m0 = blockIdx.x * 128;

    ull acc[8][4];
#pragma unroll
    for (int r = 0; r < 8; ++r)
#pragma unroll
        for (int c = 0; c < 4; ++c) acc[r][c] = 0ull;

    for (int kc = 0; kc < 16; ++kc) {
        const bool mean_part = (kc < 8);
        const int kbase = (kc & 7) * 16;
        const float* asrc = mean_part ? meanA : xdst;
        const float* bsrc = mean_part ? wl : wr;

        // A chunk: 128 rows x 16 k = 512 float4, 2 per thread, duplicated store
#pragma unroll
        for (int i = 0; i < 2; ++i) {
            int idx = t * 2 + i;
            int row = idx >> 2;   // 4 float4 per row
            int k4  = idx & 3;
            int m = m0 + row;
            float4 v = make_float4(0.f, 0.f, 0.f, 0.f);
            if (m < M) v = *(const float4*)(asrc + (long)m * H + kbase + k4 * 4);
            int kk = k4 * 4;
            *(float2*)&As2[kk + 0][2 * row] = make_float2(v.x, v.x);
            *(float2*)&As2[kk + 1][2 * row] = make_float2(v.y, v.y);
            *(float2*)&As2[kk + 2][2 * row] = make_float2(v.z, v.z);
            *(float2*)&As2[kk + 3][2 * row] = make_float2(v.w, v.w);
        }
        // B chunk: 16 k-rows x 128 = 512 float4, 2 per thread
#pragma unroll
        for (int i = 0; i < 2; ++i) {
            int idx = t * 2 + i;
            int row = idx >> 5;   // 32 float4 per k-row
            int c4  = idx & 31;
            *(float4*)&Bs[row][c4 * 4] =
                *(const float4*)(bsrc + (long)(kbase + row) * H + c4 * 4);
        }
        __syncthreads();

#pragma unroll
        for (int k = 0; k < 16; ++k) {
            const ulonglong2* ap = (const ulonglong2*)&As2[k][trow * 16];
            ulonglong2 A0 = ap[0];   // rows 0,1 broadcast pairs
            ulonglong2 A1 = ap[1];   // rows 2,3
            ulonglong2 A2 = ap[2];   // rows 4,5
            ulonglong2 A3 = ap[3];   // rows 6,7
            const ulonglong2* bp = (const ulonglong2*)&Bs[k][tcol * 8];
            ulonglong2 B0 = bp[0];   // col pairs (0,1),(2,3)
            ulonglong2 B1 = bp[1];   // col pairs (4,5),(6,7)
            ull a[8] = {A0.x, A0.y, A1.x, A1.y, A2.x, A2.y, A3.x, A3.y};
#pragma unroll
            for (int r = 0; r < 8; ++r) {
                acc[r][0] = ffma2(a[r], B0.x, acc[r][0]);
                acc[r][1] = ffma2(a[r], B0.y, acc[r][1]);
                acc[r][2] = ffma2(a[r], B1.x, acc[r][2]);
                acc[r][3] = ffma2(a[r], B1.y, acc[r][3]);
            }
        }
        __syncthreads();
    }

    // epilogue: + bias, store
#pragma unroll
    for (int r = 0; r < 8; ++r) {
        int m = m0 + trow * 8 + r;
        if (m >= M) continue;
#pragma unroll
        for (int c2 = 0; c2 < 4; c2 += 2) {
            int j = tcol * 8 + c2 * 2;
            ull p0 = acc[r][c2], p1 = acc[r][c2 + 1];
            float4 o;
            o.x = __uint_as_float((unsigned)(p0 & 0xffffffffull)) + bias[j + 0];
            o.y = __uint_as_float((unsigned)(p0 >> 32))           + bias[j + 1];
            o.z = __uint_as_float((unsigned)(p1 & 0xffffffffull)) + bias[j + 2];
            o.w = __uint_as_float((unsigned)(p1 >> 32))           + bias[j + 3];
            *(float4*)(out + (long)m * H + j) = o;
        }
    }
}

// ---------------------------------------------------------------------------
// L2-normalize each row (eps=1e-12) then relu, in place. One warp per row.
__global__ void norm_relu_kernel(float* __restrict__ x, int M) {
    int row = blockIdx.x * 8 + (threadIdx.x >> 5);
    if (row >= M) return;
    int lane = threadIdx.x & 31;
    float4* p = ((float4*)(x + (long)row * H)) + lane;
    float4 v = *p;
    float s = v.x * v.x + v.y * v.y + v.z * v.z + v.w * v.w;
#pragma unroll
    for (int o = 16; o; o >>= 1) s += __shfl_xor_sync(0xffffffffu, s, o);
    float scale = 1.0f / fmaxf(sqrtf(s), 1e-12f);
    v.x = fmaxf(v.x * scale, 0.f);
    v.y = fmaxf(v.y * scale, 0.f);
    v.z = fmaxf(v.z * scale, 0.f);
    v.w = fmaxf(v.w * scale, 0.f);
    *p = v;
}

// one warp per labeled edge: dot(xu2[src], xi2[dst])
__global__ void classifier_kernel(const float* __restrict__ xu,
                                  const float* __restrict__ xi,
                                  const int* __restrict__ lsrc,
                                  const int* __restrict__ ldst,
                                  float* __restrict__ out, int L) {
    int e = blockIdx.x * 8 + (threadIdx.x >> 5);
    if (e >= L) return;
    int lane = threadIdx.x & 31;
    int s = __ldg(&lsrc[e]);
    int d = __ldg(&ldst[e]);
    float4 a = __ldg(((const float4*)(xu + (long)s * H)) + lane);
    float4 b = __ldg(((const float4*)(xi + (long)d * H)) + lane);
    float v = a.x * b.x + a.y * b.y + a.z * b.z + a.w * b.w;
#pragma unroll
    for (int o = 16; o; o >>= 1) v += __shfl_xor_sync(0xffffffffu, v, o);
    if (lane == 0) out[e] = v;
}

// ---------------------------------------------------------------------------
extern "C" void kernel_launch(void* const* d_in, const int* in_sizes, int n_in,
                              void* d_out, int out_size) {
    const float* emb_u = (const float*)d_in[0];
    const float* emb_i = (const float*)d_in[1];
    const int* er  = (const int*)d_in[2];   // edge_rates [2, E]
    const int* erv = (const int*)d_in[3];   // edge_rev   [2, E]
    const int* lbl = (const int*)d_in[4];   // edge_label_index [2, L]
    const float* w1l_rates = (const float*)d_in[5];
    const float* w1r_rates = (const float*)d_in[6];
    const float* w1l_rev   = (const float*)d_in[7];
    const float* w1r_rev   = (const float*)d_in[8];
    const float* w2l_rates = (const float*)d_in[9];
    const float* w2r_rates = (const float*)d_in[10];
    const float* w2l_rev   = (const float*)d_in[11];
    const float* w2r_rev   = (const float*)d_in[12];
    const float* b1_rates  = (const float*)d_in[13];
    const float* b1_rev    = (const float*)d_in[14];
    const float* b2_rates  = (const float*)d_in[15];
    const float* b2_rev    = (const float*)d_in[16];
    float* out = (float*)d_out;

    const int E = in_sizes[2] / 2;
    const int L = in_sizes[4] / 2;

    float *mean, *xi1, *xu1, *xi2, *xu2;
    int *cnt, *off, *cur, *csr, *bsum;
    cudaGetSymbolAddress((void**)&mean, g_mean);
    cudaGetSymbolAddress((void**)&xi1,  g_xi1);
    cudaGetSymbolAddress((void**)&xu1,  g_xu1);
    cudaGetSymbolAddress((void**)&xi2,  g_xi2);
    cudaGetSymbolAddress((void**)&xu2,  g_xu2);
    cudaGetSymbolAddress((void**)&cnt,  g_cnt);
    cudaGetSymbolAddress((void**)&off,  g_off);
    cudaGetSymbolAddress((void**)&cur,  g_cur);
    cudaGetSymbolAddress((void**)&csr,  g_csr);
    cudaGetSymbolAddress((void**)&bsum, g_bsum);

    // index 0 = rates (dst = items), index 1 = rev (dst = users)
    int* cnt_t[2]  = {cnt, cnt + NNODE};
    int* off_t[2]  = {off, off + (NNODE + 1)};
    int* cur_t[2]  = {cur, cur + NNODE};
    int* csr_t[2]  = {csr, csr + EMAX};
    int* bsum_t[2] = {bsum, bsum + SCAN_NB};
    const int* src_t[2] = {er, erv};
    const int* dst_t[2] = {er + E, erv + E};

    const int NB_E    = (E + 255) / 256;
    const int NB_GEMM = (NNODE + 127) / 128;
    const int NB_ROWS = (NNODE + 7) / 8;
    const int NB_L    = (L + 7) / 8;
    const int NB_N    = (NNODE + 255) / 256;

    // ---- CSR build (both edge types, reused by both layers) ----
    for (int ty = 0; ty < 2; ++ty) {
        zero_int4_kernel<<<(NNODE / 4 + 255) / 256, 256>>>((int4*)cnt_t[ty], NNODE / 4);
        count_kernel<<<NB_E, 256>>>(dst_t[ty], cnt_t[ty], E);
        scan_block_kernel<<<SCAN_NB, SCAN_BS>>>(cnt_t[ty], off_t[ty], bsum_t[ty], NNODE);
        scan_sums_kernel<<<1, 128>>>(bsum_t[ty], SCAN_NB);
        finalize_off_kernel<<<NB_N, 256>>>(off_t[ty], cur_t[ty], bsum_t[ty], NNODE, E);
        fill_csr_kernel<<<NB_E, 256>>>(src_t[ty], dst_t[ty], cur_t[ty], csr_t[ty], E);
    }

    // ---- layer 1: items <- users over edge_rates ----
    gather_mean_kernel<<<NB_ROWS, 256>>>(emb_u, off_t[0], csr_t[0], mean, NNODE);
    conv_gemm_kernel<<<NB_GEMM, 256>>>(mean, emb_i, w1l_rates, w1r_rates,
                                       b1_rates, xi1, NNODE);
    norm_relu_kernel<<<NB_ROWS, 256>>>(xi1, NNODE);

    // ---- layer 1: users <- items over edge_rev ----
    gather_mean_kernel<<<NB_ROWS, 256>>>(emb_i, off_t[1], csr_t[1], mean, NNODE);
    conv_gemm_kernel<<<NB_GEMM, 256>>>(mean, emb_u, w1l_rev, w1r_rev,
                                       b1_rev, xu1, NNODE);
    norm_relu_kernel<<<NB_ROWS, 256>>>(xu1, NNODE);

    // ---- layer 2: items <- users ----
    gather_mean_kernel<<<NB_ROWS, 256>>>(xu1, off_t[0], csr_t[0], mean, NNODE);
    conv_gemm_kernel<<<NB_GEMM, 256>>>(mean, xi1, w2l_rates, w2r_rates,
                                       b2_rates, xi2, NNODE);
    norm_relu_kernel<<<NB_ROWS, 256>>>(xi2, NNODE);

    // ---- layer 2: users <- items ----
    gather_mean_kernel<<<NB_ROWS, 256>>>(xi1, off_t[1], csr_t[1], mean, NNODE);
    conv_gemm_kernel<<<NB_GEMM, 256>>>(mean, xu1, w2l_rev, w2r_rev,
                                       b2_rev, xu2, NNODE);
    norm_relu_kernel<<<NB_ROWS, 256>>>(xu2, NNODE);

    // ---- classifier ----
    classifier_kernel<<<NB_L, 256>>>(xu2, xi2, lbl, lbl + L, out, L);
}

// round 6
// speedup vs baseline: 1.4668x; 1.0428x over previous
#include <cuda_runtime.h>

#define H 128
#define NNODE 100000
#define EMAX 1600000
#define SCAN_BS 1024
#define SCAN_NB ((NNODE + SCAN_BS - 1) / SCAN_BS)   // 98

typedef unsigned long long ull;

// ---- scratch (device globals: no allocation allowed) ----
__device__ float g_mean[NNODE * H];
__device__ float g_xi1[NNODE * H];
__device__ float g_xu1[NNODE * H];
__device__ float g_xi2[NNODE * H];
__device__ float g_xu2[NNODE * H];
__device__ int g_cnt[2][NNODE];
__device__ int g_off[2][NNODE + 1];
__device__ int g_cur[2][NNODE];
__device__ int g_csr[2][EMAX];
__device__ int g_bsum[2][SCAN_NB];

// ---------------------------------------------------------------------------
__global__ void zero_int4_kernel(int4* p, int n4) {
    int i = blockIdx.x * blockDim.x + threadIdx.x;
    if (i < n4) p[i] = make_int4(0, 0, 0, 0);
}

__global__ void count_kernel(const int* __restrict__ dst, int* cnt, int E) {
    int i = blockIdx.x * blockDim.x + threadIdx.x;
    if (i < E) atomicAdd(&cnt[dst[i]], 1);
}

// phase 1: per-block exclusive scan, emit block sums
__global__ void scan_block_kernel(const int* __restrict__ cnt, int* off,
                                  int* bsum, int n) {
    __shared__ int sh[SCAN_BS];
    int tid = threadIdx.x;
    int gid = blockIdx.x * SCAN_BS + tid;
    int v = (gid < n) ? cnt[gid] : 0;
    sh[tid] = v;
    __syncthreads();
#pragma unroll
    for (int o = 1; o < SCAN_BS; o <<= 1) {
        int t = (tid >= o) ? sh[tid - o] : 0;
        __syncthreads();
        sh[tid] += t;
        __syncthreads();
    }
    if (gid < n) off[gid] = sh[tid] - v;   // exclusive
    if (tid == SCAN_BS - 1) bsum[blockIdx.x] = sh[tid];
}

// phase 2: single-block exclusive scan of block sums (nb <= 128)
__global__ void scan_sums_kernel(int* bsum, int nb) {
    __shared__ int sh[128];
    int tid = threadIdx.x;
    int v = (tid < nb) ? bsum[tid] : 0;
    sh[tid] = v;
    __syncthreads();
#pragma unroll
    for (int o = 1; o < 128; o <<= 1) {
        int t = (tid >= o) ? sh[tid - o] : 0;
        __syncthreads();
        sh[tid] += t;
        __syncthreads();
    }
    if (tid < nb) bsum[tid] = sh[tid] - v;
}

// phase 3: add block offsets; also init cursor and off[n]=E
__global__ void finalize_off_kernel(int* off, int* cur,
                                    const int* __restrict__ bsum, int n, int E) {
    int gid = blockIdx.x * blockDim.x + threadIdx.x;
    if (gid < n) {
        int o = off[gid] + bsum[gid >> 10];
        off[gid] = o;
        cur[gid] = o;
    }
    if (gid == 0) off[n] = E;
}

__global__ void fill_csr_kernel(const int* __restrict__ src,
                                const int* __restrict__ dst,
                                int* cur, int* __restrict__ csr, int E) {
    int e = blockIdx.x * blockDim.x + threadIdx.x;
    if (e >= E) return;
    int d = __ldg(&dst[e]);
    int pos = atomicAdd(&cur[d], 1);
    csr[pos] = __ldg(&src[e]);
}

// ---------------------------------------------------------------------------
// One warp per dst row: gather neighbor rows (4-way unroll -> MLP=4),
// accumulate in regs, write mean.
__global__ void gather_mean_kernel(const float* __restrict__ xsrc,
                                   const int* __restrict__ off,
                                   const int* __restrict__ csr,
                                   float* __restrict__ mean, int M) {
    int row = blockIdx.x * 8 + (threadIdx.x >> 5);
    if (row >= M) return;
    int lane = threadIdx.x & 31;
    int beg = __ldg(&off[row]);
    int end = __ldg(&off[row + 1]);
    float4 a0 = make_float4(0.f, 0.f, 0.f, 0.f);
    float4 a1 = make_float4(0.f, 0.f, 0.f, 0.f);
    float4 a2 = make_float4(0.f, 0.f, 0.f, 0.f);
    float4 a3 = make_float4(0.f, 0.f, 0.f, 0.f);
    int j = beg;
    for (; j + 3 < end; j += 4) {
        int s0 = __ldg(&csr[j + 0]);
        int s1 = __ldg(&csr[j + 1]);
        int s2 = __ldg(&csr[j + 2]);
        int s3 = __ldg(&csr[j + 3]);
        float4 v0 = __ldg(((const float4*)(xsrc + (long)s0 * H)) + lane);
        float4 v1 = __ldg(((const float4*)(xsrc + (long)s1 * H)) + lane);
        float4 v2 = __ldg(((const float4*)(xsrc + (long)s2 * H)) + lane);
        float4 v3 = __ldg(((const float4*)(xsrc + (long)s3 * H)) + lane);
        a0.x += v0.x; a0.y += v0.y; a0.z += v0.z; a0.w += v0.w;
        a1.x += v1.x; a1.y += v1.y; a1.z += v1.z; a1.w += v1.w;
        a2.x += v2.x; a2.y += v2.y; a2.z += v2.z; a2.w += v2.w;
        a3.x += v3.x; a3.y += v3.y; a3.z += v3.z; a3.w += v3.w;
    }
    for (; j < end; ++j) {
        int s0 = __ldg(&csr[j]);
        float4 v0 = __ldg(((const float4*)(xsrc + (long)s0 * H)) + lane);
        a0.x += v0.x; a0.y += v0.y; a0.z += v0.z; a0.w += v0.w;
    }
    float inv = 1.0f / fmaxf((float)(end - beg), 1.0f);
    float4 o;
    o.x = ((a0.x + a1.x) + (a2.x + a3.x)) * inv;
    o.y = ((a0.y + a1.y) + (a2.y + a3.y)) * inv;
    o.z = ((a0.z + a1.z) + (a2.z + a3.z)) * inv;
    o.w = ((a0.w + a1.w) + (a2.w + a3.w)) * inv;
    *(((float4*)(mean + (long)row * H)) + lane) = o;
}

// ---------------------------------------------------------------------------
__device__ __forceinline__ ull ffma2(ull a, ull b, ull c) {
    ull d;
    asm("fma.rn.f32x2 %0, %1, %2, %3;" : "=l"(d) : "l"(a), "l"(b), "l"(c));
    return d;
}

// Fused SAGEConv GEMM + L2-normalize + relu, packed f32x2 FMA, SW pipelined:
// out[m,:] = relu(normalize(mean[m,:] @ Wl + bias + xdst[m,:] @ Wr))
// A = [mean || xdst] (M x 256), B = [Wl ; Wr] (256 x 128)
// Tile 128x128 (full H per block -> row-norm is block-local), 256 threads,
// 8x8 per thread (4 packed col-pairs), K-chunk 16, register prefetch.
__global__ void __launch_bounds__(256, 2)
conv_gemm_kernel(const float* __restrict__ meanA,
                 const float* __restrict__ xdst,
                 const float* __restrict__ wl, const float* __restrict__ wr,
                 const float* __restrict__ bias,
                 float* __restrict__ out, int M) {
    __shared__ float As2[16][256];   // [k][2*m] duplicated pairs (16 KB)
    __shared__ float Bs[16][128];    // [k][j]                    (8 KB)

    int t = threadIdx.x;
    int tcol = t & 15;   // 16 col-groups * 8 cols
    int trow = t >> 4;   // 16 row-groups * 8 rows
    int m0 = blockIdx.x * 128;

    // A-load geometry: idx = t*2+i -> row = idx>>2 (4 float4/row), k4 = idx&3
    const int a_row0 = (t * 2 + 0) >> 2, a_k40 = (t * 2 + 0) & 3;
    const int a_row1 = (t * 2 + 1) >> 2, a_k41 = (t * 2 + 1) & 3;
    // B-load geometry: idx = t*2+i -> krow = idx>>5 (32 float4/krow), c4 = idx&31
    const int b_row0 = (t * 2 + 0) >> 5, b_c40 = (t * 2 + 0) & 31;
    const int b_row1 = (t * 2 + 1) >> 5, b_c41 = (t * 2 + 1) & 31;

    ull acc[8][4];
#pragma unroll
    for (int r = 0; r < 8; ++r)
#pragma unroll
        for (int c = 0; c < 4; ++c) acc[r][c] = 0ull;

    float4 aR0, aR1, bR0, bR1;

    // prefetch chunk 0
    {
        const float* asrc = meanA;
        const float* bsrc = wl;
        int m;
        m = m0 + a_row0;
        aR0 = (m < M) ? *(const float4*)(asrc + (long)m * H + a_k40 * 4)
                      : make_float4(0.f, 0.f, 0.f, 0.f);
        m = m0 + a_row1;
        aR1 = (m < M) ? *(const float4*)(asrc + (long)m * H + a_k41 * 4)
                      : make_float4(0.f, 0.f, 0.f, 0.f);
        bR0 = *(const float4*)(bsrc + (long)b_row0 * H + b_c40 * 4);
        bR1 = *(const float4*)(bsrc + (long)b_row1 * H + b_c41 * 4);
    }

    for (int kc = 0; kc < 16; ++kc) {
        // store current chunk to smem (A duplicated for packed broadcast)
        {
            int kk0 = a_k40 * 4;
            *(float2*)&As2[kk0 + 0][2 * a_row0] = make_float2(aR0.x, aR0.x);
            *(float2*)&As2[kk0 + 1][2 * a_row0] = make_float2(aR0.y, aR0.y);
            *(float2*)&As2[kk0 + 2][2 * a_row0] = make_float2(aR0.z, aR0.z);
            *(float2*)&As2[kk0 + 3][2 * a_row0] = make_float2(aR0.w, aR0.w);
            int kk1 = a_k41 * 4;
            *(float2*)&As2[kk1 + 0][2 * a_row1] = make_float2(aR1.x, aR1.x);
            *(float2*)&As2[kk1 + 1][2 * a_row1] = make_float2(aR1.y, aR1.y);
            *(float2*)&As2[kk1 + 2][2 * a_row1] = make_float2(aR1.z, aR1.z);
            *(float2*)&As2[kk1 + 3][2 * a_row1] = make_float2(aR1.w, aR1.w);
            *(float4*)&Bs[b_row0][b_c40 * 4] = bR0;
            *(float4*)&Bs[b_row1][b_c41 * 4] = bR1;
        }
        __syncthreads();

        // prefetch next chunk (overlaps the FFMA loop below)
        if (kc < 15) {
            int kn = kc + 1;
            const bool mp = (kn < 8);
            const int kbase = (kn & 7) * 16;
            const float* asrc = mp ? meanA : xdst;
            const float* bsrc = mp ? wl : wr;
            int m;
            m = m0 + a_row0;
            aR0 = (m < M) ? *(const float4*)(asrc + (long)m * H + kbase + a_k40 * 4)
                          : make_float4(0.f, 0.f, 0.f, 0.f);
            m = m0 + a_row1;
            aR1 = (m < M) ? *(const float4*)(asrc + (long)m * H + kbase + a_k41 * 4)
                          : make_float4(0.f, 0.f, 0.f, 0.f);
            bR0 = *(const float4*)(bsrc + (long)(kbase + b_row0) * H + b_c40 * 4);
            bR1 = *(const float4*)(bsrc + (long)(kbase + b_row1) * H + b_c41 * 4);
        }

#pragma unroll
        for (int k = 0; k < 16; ++k) {
            const ulonglong2* ap = (const ulonglong2*)&As2[k][trow * 16];
            ulonglong2 A0 = ap[0];
            ulonglong2 A1 = ap[1];
            ulonglong2 A2 = ap[2];
            ulonglong2 A3 = ap[3];
            const ulonglong2* bp = (const ulonglong2*)&Bs[k][tcol * 8];
            ulonglong2 B0 = bp[0];
            ulonglong2 B1 = bp[1];
            ull a[8] = {A0.x, A0.y, A1.x, A1.y, A2.x, A2.y, A3.x, A3.y};
#pragma unroll
            for (int r = 0; r < 8; ++r) {
                acc[r][0] = ffma2(a[r], B0.x, acc[r][0]);
                acc[r][1] = ffma2(a[r], B0.y, acc[r][1]);
                acc[r][2] = ffma2(a[r], B1.x, acc[r][2]);
                acc[r][3] = ffma2(a[r], B1.y, acc[r][3]);
            }
        }
        __syncthreads();
    }

    // ---- epilogue: + bias, row L2-norm (block-local), relu, store ----
    float bv[8];
    {
        float4 f0 = *(const float4*)(bias + tcol * 8);
        float4 f1 = *(const float4*)(bias + tcol * 8 + 4);
        bv[0] = f0.x; bv[1] = f0.y; bv[2] = f0.z; bv[3] = f0.w;
        bv[4] = f1.x; bv[5] = f1.y; bv[6] = f1.z; bv[7] = f1.w;
    }
    float vals[8][8];
#pragma unroll
    for (int r = 0; r < 8; ++r)
#pragma unroll
        for (int c2 = 0; c2 < 4; ++c2) {
            ull p = acc[r][c2];
            vals[r][2 * c2 + 0] = __uint_as_float((unsigned)(p & 0xffffffffull)) + bv[2 * c2 + 0];
            vals[r][2 * c2 + 1] = __uint_as_float((unsigned)(p >> 32)) + bv[2 * c2 + 1];
        }

    // partial sum of squares per (row, tcol) into smem (reuse As2: 128x16 floats)
    float* red = &As2[0][0];
#pragma unroll
    for (int r = 0; r < 8; ++r) {
        float p = 0.f;
#pragma unroll
        for (int c = 0; c < 8; ++c) p = fmaf(vals[r][c], vals[r][c], p);
        red[(trow * 8 + r) * 16 + tcol] = p;
    }
    __syncthreads();

#pragma unroll
    for (int r = 0; r < 8; ++r) {
        int m = m0 + trow * 8 + r;
        const float4* q = (const float4*)&red[(trow * 8 + r) * 16];
        float4 s0 = q[0], s1 = q[1], s2 = q[2], s3 = q[3];
        float s = ((s0.x + s0.y) + (s0.z + s0.w)) + ((s1.x + s1.y) + (s1.z + s1.w))
                + ((s2.x + s2.y) + (s2.z + s2.w)) + ((s3.x + s3.y) + (s3.z + s3.w));
        float scale = 1.0f / fmaxf(sqrtf(s), 1e-12f);
        if (m < M) {
            int j = tcol * 8;
            float4 o;
            o.x = fmaxf(vals[r][0] * scale, 0.f);
            o.y = fmaxf(vals[r][1] * scale, 0.f);
            o.z = fmaxf(vals[r][2] * scale, 0.f);
            o.w = fmaxf(vals[r][3] * scale, 0.f);
            *(float4*)(out + (long)m * H + j) = o;
            o.x = fmaxf(vals[r][4] * scale, 0.f);
            o.y = fmaxf(vals[r][5] * scale, 0.f);
            o.z = fmaxf(vals[r][6] * scale, 0.f);
            o.w = fmaxf(vals[r][7] * scale, 0.f);
            *(float4*)(out + (long)m * H + j + 4) = o;
        }
    }
}

// one warp per labeled edge: dot(xu2[src], xi2[dst])
__global__ void classifier_kernel(const float* __restrict__ xu,
                                  const float* __restrict__ xi,
                                  const int* __restrict__ lsrc,
                                  const int* __restrict__ ldst,
                                  float* __restrict__ out, int L) {
    int e = blockIdx.x * 8 + (threadIdx.x >> 5);
    if (e >= L) return;
    int lane = threadIdx.x & 31;
    int s = __ldg(&lsrc[e]);
    int d = __ldg(&ldst[e]);
    float4 a = __ldg(((const float4*)(xu + (long)s * H)) + lane);
    float4 b = __ldg(((const float4*)(xi + (long)d * H)) + lane);
    float v = a.x * b.x + a.y * b.y + a.z * b.z + a.w * b.w;
#pragma unroll
    for (int o = 16; o; o >>= 1) v += __shfl_xor_sync(0xffffffffu, v, o);
    if (lane == 0) out[e] = v;
}

// ---------------------------------------------------------------------------
extern "C" void kernel_launch(void* const* d_in, const int* in_sizes, int n_in,
                              void* d_out, int out_size) {
    const float* emb_u = (const float*)d_in[0];
    const float* emb_i = (const float*)d_in[1];
    const int* er  = (const int*)d_in[2];   // edge_rates [2, E]
    const int* erv = (const int*)d_in[3];   // edge_rev   [2, E]
    const int* lbl = (const int*)d_in[4];   // edge_label_index [2, L]
    const float* w1l_rates = (const float*)d_in[5];
    const float* w1r_rates = (const float*)d_in[6];
    const float* w1l_rev   = (const float*)d_in[7];
    const float* w1r_rev   = (const float*)d_in[8];
    const float* w2l_rates = (const float*)d_in[9];
    const float* w2r_rates = (const float*)d_in[10];
    const float* w2l_rev   = (const float*)d_in[11];
    const float* w2r_rev   = (const float*)d_in[12];
    const float* b1_rates  = (const float*)d_in[13];
    const float* b1_rev    = (const float*)d_in[14];
    const float* b2_rates  = (const float*)d_in[15];
    const float* b2_rev    = (const float*)d_in[16];
    float* out = (float*)d_out;

    const int E = in_sizes[2] / 2;
    const int L = in_sizes[4] / 2;

    float *mean, *xi1, *xu1, *xi2, *xu2;
    int *cnt, *off, *cur, *csr, *bsum;
    cudaGetSymbolAddress((void**)&mean, g_mean);
    cudaGetSymbolAddress((void**)&xi1,  g_xi1);
    cudaGetSymbolAddress((void**)&xu1,  g_xu1);
    cudaGetSymbolAddress((void**)&xi2,  g_xi2);
    cudaGetSymbolAddress((void**)&xu2,  g_xu2);
    cudaGetSymbolAddress((void**)&cnt,  g_cnt);
    cudaGetSymbolAddress((void**)&off,  g_off);
    cudaGetSymbolAddress((void**)&cur,  g_cur);
    cudaGetSymbolAddress((void**)&csr,  g_csr);
    cudaGetSymbolAddress((void**)&bsum, g_bsum);

    // index 0 = rates (dst = items), index 1 = rev (dst = users)
    int* cnt_t[2]  = {cnt, cnt + NNODE};
    int* off_t[2]  = {off, off + (NNODE + 1)};
    int* cur_t[2]  = {cur, cur + NNODE};
    int* csr_t[2]  = {csr, csr + EMAX};
    int* bsum_t[2] = {bsum, bsum + SCAN_NB};
    const int* src_t[2] = {er, erv};
    const int* dst_t[2] = {er + E, erv + E};

    const int NB_E    = (E + 255) / 256;
    const int NB_GEMM = (NNODE + 127) / 128;
    const int NB_ROWS = (NNODE + 7) / 8;
    const int NB_L    = (L + 7) / 8;
    const int NB_N    = (NNODE + 255) / 256;

    // ---- CSR build (both edge types, reused by both layers) ----
    for (int ty = 0; ty < 2; ++ty) {
        zero_int4_kernel<<<(NNODE / 4 + 255) / 256, 256>>>((int4*)cnt_t[ty], NNODE / 4);
        count_kernel<<<NB_E, 256>>>(dst_t[ty], cnt_t[ty], E);
        scan_block_kernel<<<SCAN_NB, SCAN_BS>>>(cnt_t[ty], off_t[ty], bsum_t[ty], NNODE);
        scan_sums_kernel<<<1, 128>>>(bsum_t[ty], SCAN_NB);
        finalize_off_kernel<<<NB_N, 256>>>(off_t[ty], cur_t[ty], bsum_t[ty], NNODE, E);
        fill_csr_kernel<<<NB_E, 256>>>(src_t[ty], dst_t[ty], cur_t[ty], csr_t[ty], E);
    }

    // ---- layer 1: items <- users over edge_rates ----
    gather_mean_kernel<<<NB_ROWS, 256>>>(emb_u, off_t[0], csr_t[0], mean, NNODE);
    conv_gemm_kernel<<<NB_GEMM, 256>>>(mean, emb_i, w1l_rates, w1r_rates,
                                       b1_rates, xi1, NNODE);

    // ---- layer 1: users <- items over edge_rev ----
    gather_mean_kernel<<<NB_ROWS, 256>>>(emb_i, off_t[1], csr_t[1], mean, NNODE);
    conv_gemm_kernel<<<NB_GEMM, 256>>>(mean, emb_u, w1l_rev, w1r_rev,
                                       b1_rev, xu1, NNODE);

    // ---- layer 2: items <- users ----
    gather_mean_kernel<<<NB_ROWS, 256>>>(xu1, off_t[0], csr_t[0], mean, NNODE);
    conv_gemm_kernel<<<NB_GEMM, 256>>>(mean, xi1, w2l_rates, w2r_rates,
                                       b2_rates, xi2, NNODE);

    // ---- layer 2: users <- items ----
    gather_mean_kernel<<<NB_ROWS, 256>>>(xi1, off_t[1], csr_t[1], mean, NNODE);
    conv_gemm_kernel<<<NB_GEMM, 256>>>(mean, xu1, w2l_rev, w2r_rev,
                                       b2_rev, xu2, NNODE);

    // ---- classifier ----
    classifier_kernel<<<NB_L, 256>>>(xu2, xi2, lbl, lbl + L, out, L);
}